// round 16
// baseline (speedup 1.0000x reference)
#include <cuda_runtime.h>
#include <cuda_fp16.h>
#include <math.h>
#include <stdint.h>

#define CD   1024
#define CH   16
#define CFF  4096
#define CB   8
#define CN   1024
#define NTOK (CB*CN)   // 8192

// ---------------- scratch (no allocations allowed) ----------------
__device__ __half g_xn_h [NTOK*CD];
__device__ float  g_xn_f [NTOK*CD];
__device__ __half g_qkv_h[NTOK*3*CD];
__device__ __half g_ao_h [NTOK*CD];
__device__ float  g_x1_f [NTOK*CD];
__device__ __half g_x2_h [NTOK*CD];
__device__ float  g_x2_f [NTOK*CD];
__device__ __half g_h_h  [NTOK*CFF];
__device__ __half g_wq_h [3*CD*CD];
__device__ __half g_wo_h [CD*CD];
__device__ __half g_w1_h [CFF*CD];
__device__ __half g_w2_h [CD*CFF];

// ---------------- helpers ----------------
__device__ __forceinline__ uint32_t smem_u32(const void* p) {
    uint32_t a;
    asm("{ .reg .u64 t; cvta.to.shared.u64 t, %1; cvt.u32.u64 %0, t; }" : "=r"(a) : "l"(p));
    return a;
}
__device__ __forceinline__ void mma_f16(float* d, const uint32_t* a, const uint32_t* b) {
    asm volatile(
        "mma.sync.aligned.m16n8k16.row.col.f32.f16.f16.f32 "
        "{%0,%1,%2,%3},{%4,%5,%6,%7},{%8,%9},{%0,%1,%2,%3};"
        : "+f"(d[0]), "+f"(d[1]), "+f"(d[2]), "+f"(d[3])
        : "r"(a[0]), "r"(a[1]), "r"(a[2]), "r"(a[3]), "r"(b[0]), "r"(b[1]));
}
__device__ __forceinline__ void ldsm_x4(uint32_t* r, uint32_t addr) {
    asm volatile("ldmatrix.sync.aligned.m8n8.x4.shared.b16 {%0,%1,%2,%3}, [%4];"
        : "=r"(r[0]), "=r"(r[1]), "=r"(r[2]), "=r"(r[3]) : "r"(addr));
}
__device__ __forceinline__ void ldsm_x4_t(uint32_t* r, uint32_t addr) {
    asm volatile("ldmatrix.sync.aligned.m8n8.x4.trans.shared.b16 {%0,%1,%2,%3}, [%4];"
        : "=r"(r[0]), "=r"(r[1]), "=r"(r[2]), "=r"(r[3]) : "r"(addr));
}
__device__ __forceinline__ uint32_t h2u(__half2 h) { return *(uint32_t*)&h; }

// ---------------- weight-rounding sizes ----------
#define NWQ4 (3*CD*CD/4)
#define NWO4 (CD*CD/4)
#define NW14 (CFF*CD/4)
#define NW24 (CD*CFF/4)
#define NALL4 (NWQ4 + NWO4 + NW14 + NW24)
#define NRBLK (NALL4/1024)

// ---------------- LN row body ------
__device__ __forceinline__ void ln_row(
    int row, int tid,
    const float* __restrict__ x, const float* __restrict__ w,
    const float* __restrict__ b, __half* __restrict__ yh, float* __restrict__ yf,
    float* sm1, float* sm2)
{
    const float4* xr = (const float4*)(x + (size_t)row * CD);
    float4 xv = xr[tid];
    float s  = xv.x + xv.y + xv.z + xv.w;
    float ss = xv.x*xv.x + xv.y*xv.y + xv.z*xv.z + xv.w*xv.w;
    #pragma unroll
    for (int o = 16; o; o >>= 1) {
        s  += __shfl_xor_sync(0xffffffffu, s,  o);
        ss += __shfl_xor_sync(0xffffffffu, ss, o);
    }
    if ((tid & 31) == 0) { sm1[tid >> 5] = s; sm2[tid >> 5] = ss; }
    __syncthreads();
    float ts = 0.f, tss = 0.f;
    #pragma unroll
    for (int i = 0; i < 8; i++) { ts += sm1[i]; tss += sm2[i]; }
    float mu   = ts * (1.0f / CD);
    float var  = tss * (1.0f / CD) - mu * mu;
    float rstd = rsqrtf(var + 1e-5f);
    float4 wv = ((const float4*)w)[tid];
    float4 bv = ((const float4*)b)[tid];
    float4 ov;
    ov.x = (xv.x - mu) * rstd * wv.x + bv.x;
    ov.y = (xv.y - mu) * rstd * wv.y + bv.y;
    ov.z = (xv.z - mu) * rstd * wv.z + bv.z;
    ov.w = (xv.w - mu) * rstd * wv.w + bv.w;
    ((float4*)(yf + (size_t)row * CD))[tid] = ov;
    uint2 oh;
    oh.x = h2u(__floats2half2_rn(ov.x, ov.y));
    oh.y = h2u(__floats2half2_rn(ov.z, ov.w));
    ((uint2*)(yh + (size_t)row * CD))[tid] = oh;
}

// ---------------- fused: LN1 + weight rounding ----------
__global__ void __launch_bounds__(256) ln1_round_k(
    const float* __restrict__ x, const float* __restrict__ n1w,
    const float* __restrict__ n1b, __half* __restrict__ yh, float* __restrict__ yf,
    const float4* __restrict__ wq, const float4* __restrict__ wo,
    const float4* __restrict__ w1, const float4* __restrict__ w2,
    uint2* __restrict__ oq, uint2* __restrict__ oo,
    uint2* __restrict__ o1, uint2* __restrict__ o2)
{
    __shared__ float sm1[8], sm2[8];
    const int tid = threadIdx.x;
    if (blockIdx.x < NTOK) {
        ln_row(blockIdx.x, tid, x, n1w, n1b, yh, yf, sm1, sm2);
        return;
    }
    int base = (blockIdx.x - NTOK) * 1024 + tid;
    float4 v[4];
    const float4* s[4]; uint2* d[4]; int j[4];
    #pragma unroll
    for (int k = 0; k < 4; k++) {
        int i = base + k * 256;
        if (i < NWQ4)                     { s[k] = wq; d[k] = oq; j[k] = i; }
        else if (i < NWQ4 + NWO4)         { s[k] = wo; d[k] = oo; j[k] = i - NWQ4; }
        else if (i < NWQ4 + NWO4 + NW14)  { s[k] = w1; d[k] = o1; j[k] = i - NWQ4 - NWO4; }
        else                              { s[k] = w2; d[k] = o2; j[k] = i - NWQ4 - NWO4 - NW14; }
        v[k] = s[k][j[k]];
    }
    #pragma unroll
    for (int k = 0; k < 4; k++) {
        uint2 o;
        o.x = h2u(__floats2half2_rn(v[k].x, v[k].y));
        o.y = h2u(__floats2half2_rn(v[k].z, v[k].w));
        d[k][j[k]] = o;
    }
}

// ---------------- standalone LayerNorm (LN2) ----------------
__global__ void __launch_bounds__(256) layernorm_k(
    const float* __restrict__ x, const float* __restrict__ w,
    const float* __restrict__ b, __half* __restrict__ yh, float* __restrict__ yf)
{
    __shared__ float sm1[8], sm2[8];
    ln_row(blockIdx.x, threadIdx.x, x, w, b, yh, yf, sm1, sm2);
}

// ---------------- fp16 mma.sync NT GEMM, templated B-tile width ----------------
// NRB = B rows per CTA tile (128 or 96).  CTA = 128 x NRB, 8 warps (32 x NRB/2).
#define NST     3
#define ROWB    144u
#define ATILE_B 18432u
#define STB(NRB)   ((128u + (unsigned)(NRB)) * 144u)
#define GSM(NRB)   (NST * STB(NRB))

template<int EPI, int NRB>
__global__ void __launch_bounds__(256, 2) gemm_mma(
    const __half* __restrict__ A, const __half* __restrict__ B,
    const float* __restrict__ bias, const float* __restrict__ res,
    void* __restrict__ Cv, int M, int N, int K)
{
    constexpr int NF   = NRB / 16;   // n-frags per warp (8 or 6)
    constexpr int NB16 = NRB / 32;   // B 16B-chunks per thread (4 or 3)
    constexpr uint32_t ST_BYTE = (128u + NRB) * 144u;

    extern __shared__ char smc[];
    const uint32_t smb = smem_u32(smc);
    const int tid  = threadIdx.x;
    const int wid  = tid >> 5;
    const int lane = tid & 31;
    const int g = lane >> 2, c = lane & 3;
    const int wy = wid & 3, wx = wid >> 2;
    const int m0 = blockIdx.y * 128;
    const int n0 = blockIdx.x * NRB;
    const int nch = K >> 6;

    const int lr = tid >> 3, lj = tid & 7;
    const __half* asrc0 = A + (size_t)(m0 + lr) * K + lj * 8;
    const __half* bsrc0 = B + (size_t)(n0 + lr) * K + lj * 8;
    const uint32_t adst0 = (uint32_t)lr * ROWB + (uint32_t)lj * 16u;
    const uint32_t bdst0 = ATILE_B + adst0;
    const size_t rstep = (size_t)32 * K;

    #pragma unroll
    for (int p = 0; p < NST - 1; p++) {
        uint32_t sb = smb + p * ST_BYTE;
        #pragma unroll
        for (int i = 0; i < 4; i++)
            asm volatile("cp.async.cg.shared.global [%0], [%1], 16;"
                :: "r"(sb + adst0 + i*4608u), "l"(asrc0 + i*rstep + p*64));
        #pragma unroll
        for (int i = 0; i < NB16; i++)
            asm volatile("cp.async.cg.shared.global [%0], [%1], 16;"
                :: "r"(sb + bdst0 + i*4608u), "l"(bsrc0 + i*rstep + p*64));
        asm volatile("cp.async.commit_group;");
    }

    float acc[2][NF][4] = {};
    const uint32_t lrow  = (uint32_t)(lane & 15);
    const uint32_t lhalf = (uint32_t)(lane >> 4);

    for (int ch = 0; ch < nch; ch++) {
        asm volatile("cp.async.wait_group %0;" :: "n"(NST - 2));
        __syncthreads();

        int ch2 = ch + NST - 1;
        if (ch2 < nch) {
            uint32_t sb = smb + (uint32_t)(ch2 % NST) * ST_BYTE;
            #pragma unroll
            for (int i = 0; i < 4; i++)
                asm volatile("cp.async.cg.shared.global [%0], [%1], 16;"
                    :: "r"(sb + adst0 + i*4608u), "l"(asrc0 + i*rstep + ch2*64));
            #pragma unroll
            for (int i = 0; i < NB16; i++)
                asm volatile("cp.async.cg.shared.global [%0], [%1], 16;"
                    :: "r"(sb + bdst0 + i*4608u), "l"(bsrc0 + i*rstep + ch2*64));
        }
        asm volatile("cp.async.commit_group;");

        const uint32_t stb   = smb + (uint32_t)(ch % NST) * ST_BYTE;
        const uint32_t abase = stb + (uint32_t)(wy * 32 + lrow) * ROWB + lhalf * 16u;
        const uint32_t bbase = stb + ATILE_B
                             + (uint32_t)(wx * (NRB/2) + lrow) * ROWB + lhalf * 16u;

        #pragma unroll
        for (int ks = 0; ks < 4; ks++) {
            uint32_t koff = (uint32_t)ks * 32u;
            uint32_t af[2][4], bf[NF][2];
            #pragma unroll
            for (int mf = 0; mf < 2; mf++)
                ldsm_x4(af[mf], abase + (uint32_t)mf * (16u * ROWB) + koff);
            #pragma unroll
            for (int np = 0; np < NF/2; np++) {
                uint32_t q[4];
                ldsm_x4(q, bbase + (uint32_t)np * (16u * ROWB) + koff);
                bf[2*np][0]   = q[0]; bf[2*np][1]   = q[2];
                bf[2*np+1][0] = q[1]; bf[2*np+1][1] = q[3];
            }
            #pragma unroll
            for (int mf = 0; mf < 2; mf++)
                #pragma unroll
                for (int nf = 0; nf < NF; nf++)
                    mma_f16(acc[mf][nf], af[mf], bf[nf]);
        }
    }

    const int mbase = m0 + wy * 32;
    const int nbase = n0 + wx * (NRB/2);
    #pragma unroll
    for (int mf = 0; mf < 2; mf++) {
        int r0 = mbase + mf * 16 + g;
        #pragma unroll
        for (int nf = 0; nf < NF; nf++) {
            int col = nbase + nf * 8 + c * 2;
            float v0 = acc[mf][nf][0], v1 = acc[mf][nf][1];
            float v2 = acc[mf][nf][2], v3 = acc[mf][nf][3];
            if (EPI >= 1) {
                float b0 = bias[col], b1 = bias[col + 1];
                v0 += b0; v1 += b1; v2 += b0; v3 += b1;
            }
            if (EPI == 1) {
                float* C = (float*)Cv;
                float2 r01 = *(const float2*)(res + (size_t)r0 * N + col);
                float2 r23 = *(const float2*)(res + (size_t)(r0 + 8) * N + col);
                *(float2*)(C + (size_t)r0 * N + col)       = make_float2(v0 + r01.x, v1 + r01.y);
                *(float2*)(C + (size_t)(r0 + 8) * N + col) = make_float2(v2 + r23.x, v3 + r23.y);
            } else {
                if (EPI == 2) {
                    v0 = v0 * normcdff(v0);
                    v1 = v1 * normcdff(v1);
                    v2 = v2 * normcdff(v2);
                    v3 = v3 * normcdff(v3);
                }
                __half* C = (__half*)Cv;
                *(uint32_t*)(C + (size_t)r0 * N + col)       = h2u(__floats2half2_rn(v0, v1));
                *(uint32_t*)(C + (size_t)(r0 + 8) * N + col) = h2u(__floats2half2_rn(v2, v3));
            }
        }
    }
}

// ---------------- Flash attention: Q via cp.async, all masks preloaded ----------
#define FH_STR 72
#define FH_QS  0
#define FH_K0  (128*FH_STR)
#define FH_V0  (FH_K0 + 3*64*FH_STR)
#define FH_END (FH_V0 + 3*64*FH_STR)        // 36864 halves = 73728 B
#define FSM_TOT (FH_END*2 + 4096 + 64)      // + mask[1024] floats
#define FSC   0.18033688f                   // 0.125 * log2(e)
#define FMK  -1.803368801e8f                // -1e9 * 0.125 * log2(e)

__global__ void __launch_bounds__(256, 2) flashm_k(
    const __half* __restrict__ qkv, const int* __restrict__ ids,
    __half* __restrict__ o)
{
    extern __shared__ char smc[];
    float*  mk  = (float*)(smc + FH_END*2);     // [1024]
    const uint32_t smb = smem_u32(smc);

    const int tid = threadIdx.x;
    const int wid = tid >> 5, lane = tid & 31;
    const int g = lane >> 2, c = lane & 3;
    const int qt = blockIdx.x, h = blockIdx.y, b = blockIdx.z;
    const int q0 = qt * 128;
    const size_t rstr = 3 * CD;

    const int lr = tid >> 3, lj = tid & 7;
    const uint32_t kvoff = (uint32_t)lr * 144u + (uint32_t)lj * 16u;
    const __half* kvsrc = qkv + ((size_t)(b*CN + lr)) * rstr + CD + h*64 + lj*8;

    // ---- prologue: Q tile via cp.async (own group, committed first) ----
    {
        const __half* qsrc = qkv + ((size_t)(b*CN + q0 + lr)) * rstr + h*64 + lj*8;
        #pragma unroll
        for (int i = 0; i < 4; i++)
            asm volatile("cp.async.cg.shared.global [%0], [%1], 16;"
                :: "r"(smb + kvoff + i*4608u), "l"(qsrc + (size_t)i*32*rstr));
        asm volatile("cp.async.commit_group;");
    }
    // K/V stages 0,1
    #pragma unroll
    for (int p = 0; p < 2; p++) {
        const __half* src = kvsrc + (size_t)(p * 64) * rstr;
        const uint32_t kd0 = smb + (FH_K0 + p*4608)*2 + kvoff;
        const uint32_t vd0 = smb + (FH_V0 + p*4608)*2 + kvoff;
        #pragma unroll
        for (int i = 0; i < 2; i++) {
            asm volatile("cp.async.cg.shared.global [%0], [%1], 16;"
                :: "r"(kd0 + i*4608u), "l"(src + (size_t)i*32*rstr));
            asm volatile("cp.async.cg.shared.global [%0], [%1], 16;"
                :: "r"(vd0 + i*4608u), "l"(src + (size_t)i*32*rstr + CD));
        }
        asm volatile("cp.async.commit_group;");
    }
    // all masks for this batch, once
    for (int i = tid; i < CN; i += 256)
        mk[i] = FMK * (float)ids[b*CN + i];

    asm volatile("cp.async.wait_group 2;");   // Q group done; stages 0,1 may be pending
    __syncthreads();

    // hoist Q fragments
    const uint32_t lrow  = (uint32_t)(lane & 15);
    const uint32_t lhalf = (uint32_t)(lane >> 4);
    uint32_t qf[4][4];
    {
        const uint32_t qbase = smb + (uint32_t)(wid*16 + lrow) * 144u + lhalf * 16u;
        #pragma unroll
        for (int ks = 0; ks < 4; ks++)
            ldsm_x4(qf[ks], qbase + (uint32_t)ks * 32u);
    }

    // hoisted per-stage ldmatrix bases and cp.async destinations
    uint32_t kb[3], vb[3], kd[3], vd[3];
    #pragma unroll
    for (int s = 0; s < 3; s++) {
        kb[s] = smb + (uint32_t)(FH_K0 + s*4608)*2 + lrow * 144u + lhalf * 16u;
        vb[s] = smb + (uint32_t)(FH_V0 + s*4608)*2 + lrow * 144u + lhalf * 16u;
        kd[s] = smb + (uint32_t)(FH_K0 + s*4608)*2 + kvoff;
        vd[s] = smb + (uint32_t)(FH_V0 + s*4608)*2 + kvoff;
    }

    float oa[8][4] = {};
    float m0 = -1e30f, m1 = -1e30f, l0 = 0.f, l1 = 0.f;

    int st = 0;
    for (int kt = 0; kt < 16; kt++) {
        asm volatile("cp.async.wait_group 1;");
        __syncthreads();

        if (kt < 14) {
            const int s2 = (st + 2 >= 3) ? st - 1 : st + 2;
            const int k2 = (kt + 2) * 64;
            const __half* src = kvsrc + (size_t)k2 * rstr;
            #pragma unroll
            for (int i = 0; i < 2; i++) {
                asm volatile("cp.async.cg.shared.global [%0], [%1], 16;"
                    :: "r"(kd[s2] + i*4608u), "l"(src + (size_t)i*32*rstr));
                asm volatile("cp.async.cg.shared.global [%0], [%1], 16;"
                    :: "r"(vd[s2] + i*4608u), "l"(src + (size_t)i*32*rstr + CD));
            }
        }
        asm volatile("cp.async.commit_group;");

        const uint32_t kbase = kb[st];
        const uint32_t vbase = vb[st];
        const float* mkc = mk + kt * 64;

        // ---- S = Q @ K^T ----
        float sa[8][4] = {};
        #pragma unroll
        for (int ks = 0; ks < 4; ks++) {
            #pragma unroll
            for (int np = 0; np < 4; np++) {
                uint32_t q[4];
                ldsm_x4(q, kbase + (uint32_t)np * (16u*144u) + (uint32_t)ks * 32u);
                uint32_t b0[2] = {q[0], q[2]}, b1[2] = {q[1], q[3]};
                mma_f16(sa[2*np],   qf[ks], b0);
                mma_f16(sa[2*np+1], qf[ks], b1);
            }
        }

        // ---- scale+mask (log2 domain) + online softmax via exp2 ----
        float rmax0 = -1e30f, rmax1 = -1e30f;
        #pragma unroll
        for (int nf = 0; nf < 8; nf++) {
            float mv0 = mkc[nf*8 + 2*c], mv1 = mkc[nf*8 + 2*c + 1];
            sa[nf][0] = fmaf(sa[nf][0], FSC, mv0); sa[nf][1] = fmaf(sa[nf][1], FSC, mv1);
            sa[nf][2] = fmaf(sa[nf][2], FSC, mv0); sa[nf][3] = fmaf(sa[nf][3], FSC, mv1);
            rmax0 = fmaxf(rmax0, fmaxf(sa[nf][0], sa[nf][1]));
            rmax1 = fmaxf(rmax1, fmaxf(sa[nf][2], sa[nf][3]));
        }
        rmax0 = fmaxf(rmax0, __shfl_xor_sync(0xffffffffu, rmax0, 1));
        rmax0 = fmaxf(rmax0, __shfl_xor_sync(0xffffffffu, rmax0, 2));
        rmax1 = fmaxf(rmax1, __shfl_xor_sync(0xffffffffu, rmax1, 1));
        rmax1 = fmaxf(rmax1, __shfl_xor_sync(0xffffffffu, rmax1, 2));
        float mn0 = fmaxf(m0, rmax0), mn1 = fmaxf(m1, rmax1);
        float al0 = exp2f(m0 - mn0), al1 = exp2f(m1 - mn1);
        m0 = mn0; m1 = mn1;
        float ps0 = 0.f, ps1 = 0.f;
        #pragma unroll
        for (int nf = 0; nf < 8; nf++) {
            float p0 = exp2f(sa[nf][0] - mn0);
            float p1 = exp2f(sa[nf][1] - mn0);
            float p2 = exp2f(sa[nf][2] - mn1);
            float p3 = exp2f(sa[nf][3] - mn1);
            ps0 += p0 + p1; ps1 += p2 + p3;
            sa[nf][0] = p0; sa[nf][1] = p1; sa[nf][2] = p2; sa[nf][3] = p3;
        }
        ps0 += __shfl_xor_sync(0xffffffffu, ps0, 1);
        ps0 += __shfl_xor_sync(0xffffffffu, ps0, 2);
        ps1 += __shfl_xor_sync(0xffffffffu, ps1, 1);
        ps1 += __shfl_xor_sync(0xffffffffu, ps1, 2);
        l0 = l0 * al0 + ps0;
        l1 = l1 * al1 + ps1;
        #pragma unroll
        for (int nf = 0; nf < 8; nf++) {
            oa[nf][0] *= al0; oa[nf][1] *= al0;
            oa[nf][2] *= al1; oa[nf][3] *= al1;
        }

        // ---- O += P @ V ----
        #pragma unroll
        for (int ks = 0; ks < 4; ks++) {
            uint32_t a[4];
            a[0] = h2u(__floats2half2_rn(sa[2*ks][0],   sa[2*ks][1]));
            a[1] = h2u(__floats2half2_rn(sa[2*ks][2],   sa[2*ks][3]));
            a[2] = h2u(__floats2half2_rn(sa[2*ks+1][0], sa[2*ks+1][1]));
            a[3] = h2u(__floats2half2_rn(sa[2*ks+1][2], sa[2*ks+1][3]));
            #pragma unroll
            for (int np = 0; np < 4; np++) {
                uint32_t q[4];
                ldsm_x4_t(q, vbase + (uint32_t)ks * (16u*144u) + (uint32_t)np * 32u);
                uint32_t b0[2] = {q[0], q[1]}, b1[2] = {q[2], q[3]};
                mma_f16(oa[2*np],   a, b0);
                mma_f16(oa[2*np+1], a, b1);
            }
        }

        st = (st + 1 >= 3) ? 0 : st + 1;
    }

    // ---- epilogue ----
    float inv0 = 1.0f / l0, inv1 = 1.0f / l1;
    size_t r0 = (size_t)(b*CN + q0 + wid*16 + g) * CD + h*64;
    size_t r1 = (size_t)(b*CN + q0 + wid*16 + g + 8) * CD + h*64;
    #pragma unroll
    for (int nf = 0; nf < 8; nf++) {
        int col = nf*8 + 2*c;
        *(uint32_t*)(o + r0 + col) = h2u(__floats2half2_rn(oa[nf][0]*inv0, oa[nf][1]*inv0));
        *(uint32_t*)(o + r1 + col) = h2u(__floats2half2_rn(oa[nf][2]*inv1, oa[nf][3]*inv1));
    }
}

// ---------------- launch ----------------
extern "C" void kernel_launch(void* const* d_in, const int* in_sizes, int n_in,
                              void* d_out, int out_size)
{
    const float* x      = (const float*)d_in[0];
    const int*   ids    = (const int*)  d_in[1];
    const float* n1w    = (const float*)d_in[2];
    const float* n1b    = (const float*)d_in[3];
    const float* pin_w  = (const float*)d_in[4];
    const float* pout_w = (const float*)d_in[5];
    const float* pout_b = (const float*)d_in[6];
    const float* n2w    = (const float*)d_in[7];
    const float* n2b    = (const float*)d_in[8];
    const float* l1w    = (const float*)d_in[9];
    const float* l1b    = (const float*)d_in[10];
    const float* l2w    = (const float*)d_in[11];
    const float* l2b    = (const float*)d_in[12];
    float* out = (float*)d_out;

    __half *xnh, *qkvh, *aoh, *x2h, *hhh, *wqh, *woh, *w1h, *w2h;
    float *xnf, *x1f, *x2f;
    cudaGetSymbolAddress((void**)&xnh,  g_xn_h);
    cudaGetSymbolAddress((void**)&xnf,  g_xn_f);
    cudaGetSymbolAddress((void**)&qkvh, g_qkv_h);
    cudaGetSymbolAddress((void**)&aoh,  g_ao_h);
    cudaGetSymbolAddress((void**)&x1f,  g_x1_f);
    cudaGetSymbolAddress((void**)&x2h,  g_x2_h);
    cudaGetSymbolAddress((void**)&x2f,  g_x2_f);
    cudaGetSymbolAddress((void**)&hhh,  g_h_h);
    cudaGetSymbolAddress((void**)&wqh,  g_wq_h);
    cudaGetSymbolAddress((void**)&woh,  g_wo_h);
    cudaGetSymbolAddress((void**)&w1h,  g_w1_h);
    cudaGetSymbolAddress((void**)&w2h,  g_w2_h);

    cudaFuncSetAttribute(flashm_k,         cudaFuncAttributeMaxDynamicSharedMemorySize, FSM_TOT);
    cudaFuncSetAttribute(gemm_mma<0,96>,   cudaFuncAttributeMaxDynamicSharedMemorySize, GSM(96));
    cudaFuncSetAttribute(gemm_mma<1,128>,  cudaFuncAttributeMaxDynamicSharedMemorySize, GSM(128));
    cudaFuncSetAttribute(gemm_mma<2,128>,  cudaFuncAttributeMaxDynamicSharedMemorySize, GSM(128));

    // 0+1) fused: LN1 + weights->fp16
    ln1_round_k<<<NTOK + NRBLK, 256>>>(
        x, n1w, n1b, xnh, xnf,
        (const float4*)pin_w, (const float4*)pout_w, (const float4*)l1w, (const float4*)l2w,
        (uint2*)wqh, (uint2*)woh, (uint2*)w1h, (uint2*)w2h);

    // 2) qkv = xn @ Wq^T  (fp16 out) — N-tile 96 for 98.8% wave fill
    gemm_mma<0,96><<<dim3(3*CD/96, NTOK/128), 256, GSM(96)>>>(xnh, wqh, nullptr, nullptr, qkvh, NTOK, 3*CD, CD);
    // 3) flash attention -> ao (fp16)
    flashm_k<<<dim3(CN/128, CH, CB), 256, FSM_TOT>>>(qkvh, ids, aoh);
    // 4) x1 = ao @ Wo^T + bout + xn  (fp32 out)
    gemm_mma<1,128><<<dim3(CD/128, NTOK/128), 256, GSM(128)>>>(aoh, woh, pout_b, xnf, x1f, NTOK, CD, CD);
    // 5) x2 = LN2(x1)
    layernorm_k<<<NTOK, 256>>>(x1f, n2w, n2b, x2h, x2f);
    // 6) h = gelu(x2 @ W1^T + b1)  (fp16 out)
    gemm_mma<2,128><<<dim3(CFF/128, NTOK/128), 256, GSM(128)>>>(x2h, w1h, l1b, nullptr, hhh, NTOK, CFF, CD);
    // 7) out = h @ W2^T + b2 + x2  (fp32 out)
    gemm_mma<1,128><<<dim3(CD/128, NTOK/128), 256, GSM(128)>>>(hhh, w2h, l2b, x2f, out, NTOK, CD, CFF);
}

// round 17
// speedup vs baseline: 1.0032x; 1.0032x over previous
#include <cuda_runtime.h>
#include <cuda_fp16.h>
#include <math.h>
#include <stdint.h>

#define CD   1024
#define CH   16
#define CFF  4096
#define CB   8
#define CN   1024
#define NTOK (CB*CN)   // 8192

// ---------------- scratch (no allocations allowed) ----------------
__device__ __half g_xn_h [NTOK*CD];
__device__ float  g_xn_f [NTOK*CD];
__device__ __half g_qkv_h[NTOK*3*CD];
__device__ __half g_ao_h [NTOK*CD];
__device__ float  g_x1_f [NTOK*CD];
__device__ __half g_x2_h [NTOK*CD];
__device__ float  g_x2_f [NTOK*CD];
__device__ __half g_h_h  [NTOK*CFF];
__device__ __half g_wq_h [3*CD*CD];
__device__ __half g_wo_h [CD*CD];
__device__ __half g_w1_h [CFF*CD];
__device__ __half g_w2_h [CD*CFF];

// ---------------- helpers ----------------
__device__ __forceinline__ uint32_t smem_u32(const void* p) {
    uint32_t a;
    asm("{ .reg .u64 t; cvta.to.shared.u64 t, %1; cvt.u32.u64 %0, t; }" : "=r"(a) : "l"(p));
    return a;
}
__device__ __forceinline__ void mma_f16(float* d, const uint32_t* a, const uint32_t* b) {
    asm volatile(
        "mma.sync.aligned.m16n8k16.row.col.f32.f16.f16.f32 "
        "{%0,%1,%2,%3},{%4,%5,%6,%7},{%8,%9},{%0,%1,%2,%3};"
        : "+f"(d[0]), "+f"(d[1]), "+f"(d[2]), "+f"(d[3])
        : "r"(a[0]), "r"(a[1]), "r"(a[2]), "r"(a[3]), "r"(b[0]), "r"(b[1]));
}
__device__ __forceinline__ void ldsm_x4(uint32_t* r, uint32_t addr) {
    asm volatile("ldmatrix.sync.aligned.m8n8.x4.shared.b16 {%0,%1,%2,%3}, [%4];"
        : "=r"(r[0]), "=r"(r[1]), "=r"(r[2]), "=r"(r[3]) : "r"(addr));
}
__device__ __forceinline__ void ldsm_x4_t(uint32_t* r, uint32_t addr) {
    asm volatile("ldmatrix.sync.aligned.m8n8.x4.trans.shared.b16 {%0,%1,%2,%3}, [%4];"
        : "=r"(r[0]), "=r"(r[1]), "=r"(r[2]), "=r"(r[3]) : "r"(addr));
}
__device__ __forceinline__ uint32_t h2u(__half2 h) { return *(uint32_t*)&h; }

// ---------------- weight-rounding sizes ----------
#define NWQ4 (3*CD*CD/4)
#define NWO4 (CD*CD/4)
#define NW14 (CFF*CD/4)
#define NW24 (CD*CFF/4)
#define NALL4 (NWQ4 + NWO4 + NW14 + NW24)
#define NRBLK (NALL4/1024)

// ---------------- LN row body ------
__device__ __forceinline__ void ln_row(
    int row, int tid,
    const float* __restrict__ x, const float* __restrict__ w,
    const float* __restrict__ b, __half* __restrict__ yh, float* __restrict__ yf,
    float* sm1, float* sm2)
{
    const float4* xr = (const float4*)(x + (size_t)row * CD);
    float4 xv = xr[tid];
    float s  = xv.x + xv.y + xv.z + xv.w;
    float ss = xv.x*xv.x + xv.y*xv.y + xv.z*xv.z + xv.w*xv.w;
    #pragma unroll
    for (int o = 16; o; o >>= 1) {
        s  += __shfl_xor_sync(0xffffffffu, s,  o);
        ss += __shfl_xor_sync(0xffffffffu, ss, o);
    }
    if ((tid & 31) == 0) { sm1[tid >> 5] = s; sm2[tid >> 5] = ss; }
    __syncthreads();
    float ts = 0.f, tss = 0.f;
    #pragma unroll
    for (int i = 0; i < 8; i++) { ts += sm1[i]; tss += sm2[i]; }
    float mu   = ts * (1.0f / CD);
    float var  = tss * (1.0f / CD) - mu * mu;
    float rstd = rsqrtf(var + 1e-5f);
    float4 wv = ((const float4*)w)[tid];
    float4 bv = ((const float4*)b)[tid];
    float4 ov;
    ov.x = (xv.x - mu) * rstd * wv.x + bv.x;
    ov.y = (xv.y - mu) * rstd * wv.y + bv.y;
    ov.z = (xv.z - mu) * rstd * wv.z + bv.z;
    ov.w = (xv.w - mu) * rstd * wv.w + bv.w;
    ((float4*)(yf + (size_t)row * CD))[tid] = ov;
    uint2 oh;
    oh.x = h2u(__floats2half2_rn(ov.x, ov.y));
    oh.y = h2u(__floats2half2_rn(ov.z, ov.w));
    ((uint2*)(yh + (size_t)row * CD))[tid] = oh;
}

// ---------------- fused: LN1 + weight rounding ----------
__global__ void __launch_bounds__(256) ln1_round_k(
    const float* __restrict__ x, const float* __restrict__ n1w,
    const float* __restrict__ n1b, __half* __restrict__ yh, float* __restrict__ yf,
    const float4* __restrict__ wq, const float4* __restrict__ wo,
    const float4* __restrict__ w1, const float4* __restrict__ w2,
    uint2* __restrict__ oq, uint2* __restrict__ oo,
    uint2* __restrict__ o1, uint2* __restrict__ o2)
{
    __shared__ float sm1[8], sm2[8];
    const int tid = threadIdx.x;
    if (blockIdx.x < NTOK) {
        ln_row(blockIdx.x, tid, x, n1w, n1b, yh, yf, sm1, sm2);
        return;
    }
    int base = (blockIdx.x - NTOK) * 1024 + tid;
    float4 v[4];
    const float4* s[4]; uint2* d[4]; int j[4];
    #pragma unroll
    for (int k = 0; k < 4; k++) {
        int i = base + k * 256;
        if (i < NWQ4)                     { s[k] = wq; d[k] = oq; j[k] = i; }
        else if (i < NWQ4 + NWO4)         { s[k] = wo; d[k] = oo; j[k] = i - NWQ4; }
        else if (i < NWQ4 + NWO4 + NW14)  { s[k] = w1; d[k] = o1; j[k] = i - NWQ4 - NWO4; }
        else                              { s[k] = w2; d[k] = o2; j[k] = i - NWQ4 - NWO4 - NW14; }
        v[k] = s[k][j[k]];
    }
    #pragma unroll
    for (int k = 0; k < 4; k++) {
        uint2 o;
        o.x = h2u(__floats2half2_rn(v[k].x, v[k].y));
        o.y = h2u(__floats2half2_rn(v[k].z, v[k].w));
        d[k][j[k]] = o;
    }
}

// ---------------- standalone LayerNorm (LN2) ----------------
__global__ void __launch_bounds__(256) layernorm_k(
    const float* __restrict__ x, const float* __restrict__ w,
    const float* __restrict__ b, __half* __restrict__ yh, float* __restrict__ yf)
{
    __shared__ float sm1[8], sm2[8];
    ln_row(blockIdx.x, threadIdx.x, x, w, b, yh, yf, sm1, sm2);
}

// ---------------- fp16 mma.sync NT GEMM, 2 CTAs/SM (R9/R15, proven) ----------------
#define NST     3
#define ROWB    144u
#define ATILE_B 18432u
#define ST_BYTE (2u*ATILE_B)
#define GSMEM   (NST*ST_BYTE)          // 110592

template<int EPI>
__global__ void __launch_bounds__(256, 2) gemm_mma(
    const __half* __restrict__ A, const __half* __restrict__ B,
    const float* __restrict__ bias, const float* __restrict__ res,
    void* __restrict__ Cv, int M, int N, int K)
{
    extern __shared__ char smc[];
    const uint32_t smb = smem_u32(smc);
    const int tid  = threadIdx.x;
    const int wid  = tid >> 5;
    const int lane = tid & 31;
    const int g = lane >> 2, c = lane & 3;
    const int wy = wid & 3, wx = wid >> 2;
    const int m0 = blockIdx.y * 128;
    const int n0 = blockIdx.x * 128;
    const int nch = K >> 6;

    const int lr = tid >> 3, lj = tid & 7;
    const __half* asrc0 = A + (size_t)(m0 + lr) * K + lj * 8;
    const __half* bsrc0 = B + (size_t)(n0 + lr) * K + lj * 8;
    const uint32_t adst0 = (uint32_t)lr * ROWB + (uint32_t)lj * 16u;
    const uint32_t bdst0 = ATILE_B + adst0;
    const size_t rstep = (size_t)32 * K;

    #pragma unroll
    for (int p = 0; p < NST - 1; p++) {
        uint32_t sb = smb + p * ST_BYTE;
        #pragma unroll
        for (int i = 0; i < 4; i++) {
            asm volatile("cp.async.cg.shared.global [%0], [%1], 16;"
                :: "r"(sb + adst0 + i*4608u), "l"(asrc0 + i*rstep + p*64));
            asm volatile("cp.async.cg.shared.global [%0], [%1], 16;"
                :: "r"(sb + bdst0 + i*4608u), "l"(bsrc0 + i*rstep + p*64));
        }
        asm volatile("cp.async.commit_group;");
    }

    float acc[2][8][4] = {};
    const uint32_t lrow  = (uint32_t)(lane & 15);
    const uint32_t lhalf = (uint32_t)(lane >> 4);

    for (int ch = 0; ch < nch; ch++) {
        asm volatile("cp.async.wait_group %0;" :: "n"(NST - 2));
        __syncthreads();

        int ch2 = ch + NST - 1;
        if (ch2 < nch) {
            uint32_t sb = smb + (uint32_t)(ch2 % NST) * ST_BYTE;
            #pragma unroll
            for (int i = 0; i < 4; i++) {
                asm volatile("cp.async.cg.shared.global [%0], [%1], 16;"
                    :: "r"(sb + adst0 + i*4608u), "l"(asrc0 + i*rstep + ch2*64));
                asm volatile("cp.async.cg.shared.global [%0], [%1], 16;"
                    :: "r"(sb + bdst0 + i*4608u), "l"(bsrc0 + i*rstep + ch2*64));
            }
        }
        asm volatile("cp.async.commit_group;");

        const uint32_t stb   = smb + (uint32_t)(ch % NST) * ST_BYTE;
        const uint32_t abase = stb + (uint32_t)(wy * 32 + lrow) * ROWB + lhalf * 16u;
        const uint32_t bbase = stb + ATILE_B
                             + (uint32_t)(wx * 64 + lrow) * ROWB + lhalf * 16u;

        #pragma unroll
        for (int ks = 0; ks < 4; ks++) {
            uint32_t koff = (uint32_t)ks * 32u;
            uint32_t af[2][4], bf[8][2];
            #pragma unroll
            for (int mf = 0; mf < 2; mf++)
                ldsm_x4(af[mf], abase + (uint32_t)mf * (16u * ROWB) + koff);
            #pragma unroll
            for (int np = 0; np < 4; np++) {
                uint32_t q[4];
                ldsm_x4(q, bbase + (uint32_t)np * (16u * ROWB) + koff);
                bf[2*np][0]   = q[0]; bf[2*np][1]   = q[2];
                bf[2*np+1][0] = q[1]; bf[2*np+1][1] = q[3];
            }
            #pragma unroll
            for (int mf = 0; mf < 2; mf++)
                #pragma unroll
                for (int nf = 0; nf < 8; nf++)
                    mma_f16(acc[mf][nf], af[mf], bf[nf]);
        }
    }

    const int mbase = m0 + wy * 32;
    const int nbase = n0 + wx * 64;
    #pragma unroll
    for (int mf = 0; mf < 2; mf++) {
        int r0 = mbase + mf * 16 + g;
        #pragma unroll
        for (int nf = 0; nf < 8; nf++) {
            int col = nbase + nf * 8 + c * 2;
            float v0 = acc[mf][nf][0], v1 = acc[mf][nf][1];
            float v2 = acc[mf][nf][2], v3 = acc[mf][nf][3];
            if (EPI >= 1) {
                float b0 = bias[col], b1 = bias[col + 1];
                v0 += b0; v1 += b1; v2 += b0; v3 += b1;
            }
            if (EPI == 1) {
                float* C = (float*)Cv;
                float2 r01 = *(const float2*)(res + (size_t)r0 * N + col);
                float2 r23 = *(const float2*)(res + (size_t)(r0 + 8) * N + col);
                *(float2*)(C + (size_t)r0 * N + col)       = make_float2(v0 + r01.x, v1 + r01.y);
                *(float2*)(C + (size_t)(r0 + 8) * N + col) = make_float2(v2 + r23.x, v3 + r23.y);
            } else {
                if (EPI == 2) {
                    v0 = v0 * normcdff(v0);
                    v1 = v1 * normcdff(v1);
                    v2 = v2 * normcdff(v2);
                    v3 = v3 * normcdff(v3);
                }
                __half* C = (__half*)Cv;
                *(uint32_t*)(C + (size_t)r0 * N + col)       = h2u(__floats2half2_rn(v0, v1));
                *(uint32_t*)(C + (size_t)(r0 + 8) * N + col) = h2u(__floats2half2_rn(v2, v3));
            }
        }
    }
}

// ---------------- Flash attention (R16: Q via cp.async, masks preloaded) ----------
#define FH_STR 72
#define FH_QS  0
#define FH_K0  (128*FH_STR)
#define FH_V0  (FH_K0 + 3*64*FH_STR)
#define FH_END (FH_V0 + 3*64*FH_STR)        // 36864 halves = 73728 B
#define FSM_TOT (FH_END*2 + 4096 + 64)      // + mask[1024] floats
#define FSC   0.18033688f                   // 0.125 * log2(e)
#define FMK  -1.803368801e8f                // -1e9 * 0.125 * log2(e)

__global__ void __launch_bounds__(256, 2) flashm_k(
    const __half* __restrict__ qkv, const int* __restrict__ ids,
    __half* __restrict__ o)
{
    extern __shared__ char smc[];
    float*  mk  = (float*)(smc + FH_END*2);     // [1024]
    const uint32_t smb = smem_u32(smc);

    const int tid = threadIdx.x;
    const int wid = tid >> 5, lane = tid & 31;
    const int g = lane >> 2, c = lane & 3;
    const int qt = blockIdx.x, h = blockIdx.y, b = blockIdx.z;
    const int q0 = qt * 128;
    const size_t rstr = 3 * CD;

    const int lr = tid >> 3, lj = tid & 7;
    const uint32_t kvoff = (uint32_t)lr * 144u + (uint32_t)lj * 16u;
    const __half* kvsrc = qkv + ((size_t)(b*CN + lr)) * rstr + CD + h*64 + lj*8;

    // ---- prologue: Q tile via cp.async (own group, committed first) ----
    {
        const __half* qsrc = qkv + ((size_t)(b*CN + q0 + lr)) * rstr + h*64 + lj*8;
        #pragma unroll
        for (int i = 0; i < 4; i++)
            asm volatile("cp.async.cg.shared.global [%0], [%1], 16;"
                :: "r"(smb + kvoff + i*4608u), "l"(qsrc + (size_t)i*32*rstr));
        asm volatile("cp.async.commit_group;");
    }
    // K/V stages 0,1
    #pragma unroll
    for (int p = 0; p < 2; p++) {
        const __half* src = kvsrc + (size_t)(p * 64) * rstr;
        const uint32_t kd0 = smb + (FH_K0 + p*4608)*2 + kvoff;
        const uint32_t vd0 = smb + (FH_V0 + p*4608)*2 + kvoff;
        #pragma unroll
        for (int i = 0; i < 2; i++) {
            asm volatile("cp.async.cg.shared.global [%0], [%1], 16;"
                :: "r"(kd0 + i*4608u), "l"(src + (size_t)i*32*rstr));
            asm volatile("cp.async.cg.shared.global [%0], [%1], 16;"
                :: "r"(vd0 + i*4608u), "l"(src + (size_t)i*32*rstr + CD));
        }
        asm volatile("cp.async.commit_group;");
    }
    // all masks for this batch, once
    for (int i = tid; i < CN; i += 256)
        mk[i] = FMK * (float)ids[b*CN + i];

    asm volatile("cp.async.wait_group 2;");   // Q group done
    __syncthreads();

    // hoist Q fragments
    const uint32_t lrow  = (uint32_t)(lane & 15);
    const uint32_t lhalf = (uint32_t)(lane >> 4);
    uint32_t qf[4][4];
    {
        const uint32_t qbase = smb + (uint32_t)(wid*16 + lrow) * 144u + lhalf * 16u;
        #pragma unroll
        for (int ks = 0; ks < 4; ks++)
            ldsm_x4(qf[ks], qbase + (uint32_t)ks * 32u);
    }

    // hoisted per-stage ldmatrix bases and cp.async destinations
    uint32_t kb[3], vb[3], kd[3], vd[3];
    #pragma unroll
    for (int s = 0; s < 3; s++) {
        kb[s] = smb + (uint32_t)(FH_K0 + s*4608)*2 + lrow * 144u + lhalf * 16u;
        vb[s] = smb + (uint32_t)(FH_V0 + s*4608)*2 + lrow * 144u + lhalf * 16u;
        kd[s] = smb + (uint32_t)(FH_K0 + s*4608)*2 + kvoff;
        vd[s] = smb + (uint32_t)(FH_V0 + s*4608)*2 + kvoff;
    }

    float oa[8][4] = {};
    float m0 = -1e30f, m1 = -1e30f, l0 = 0.f, l1 = 0.f;

    int st = 0;
    for (int kt = 0; kt < 16; kt++) {
        asm volatile("cp.async.wait_group 1;");
        __syncthreads();

        if (kt < 14) {
            const int s2 = (st + 2 >= 3) ? st - 1 : st + 2;
            const int k2 = (kt + 2) * 64;
            const __half* src = kvsrc + (size_t)k2 * rstr;
            #pragma unroll
            for (int i = 0; i < 2; i++) {
                asm volatile("cp.async.cg.shared.global [%0], [%1], 16;"
                    :: "r"(kd[s2] + i*4608u), "l"(src + (size_t)i*32*rstr));
                asm volatile("cp.async.cg.shared.global [%0], [%1], 16;"
                    :: "r"(vd[s2] + i*4608u), "l"(src + (size_t)i*32*rstr + CD));
            }
        }
        asm volatile("cp.async.commit_group;");

        const uint32_t kbase = kb[st];
        const uint32_t vbase = vb[st];
        const float* mkc = mk + kt * 64;

        // ---- S = Q @ K^T ----
        float sa[8][4] = {};
        #pragma unroll
        for (int ks = 0; ks < 4; ks++) {
            #pragma unroll
            for (int np = 0; np < 4; np++) {
                uint32_t q[4];
                ldsm_x4(q, kbase + (uint32_t)np * (16u*144u) + (uint32_t)ks * 32u);
                uint32_t b0[2] = {q[0], q[2]}, b1[2] = {q[1], q[3]};
                mma_f16(sa[2*np],   qf[ks], b0);
                mma_f16(sa[2*np+1], qf[ks], b1);
            }
        }

        // ---- scale+mask (log2 domain) + online softmax via exp2 ----
        float rmax0 = -1e30f, rmax1 = -1e30f;
        #pragma unroll
        for (int nf = 0; nf < 8; nf++) {
            float mv0 = mkc[nf*8 + 2*c], mv1 = mkc[nf*8 + 2*c + 1];
            sa[nf][0] = fmaf(sa[nf][0], FSC, mv0); sa[nf][1] = fmaf(sa[nf][1], FSC, mv1);
            sa[nf][2] = fmaf(sa[nf][2], FSC, mv0); sa[nf][3] = fmaf(sa[nf][3], FSC, mv1);
            rmax0 = fmaxf(rmax0, fmaxf(sa[nf][0], sa[nf][1]));
            rmax1 = fmaxf(rmax1, fmaxf(sa[nf][2], sa[nf][3]));
        }
        rmax0 = fmaxf(rmax0, __shfl_xor_sync(0xffffffffu, rmax0, 1));
        rmax0 = fmaxf(rmax0, __shfl_xor_sync(0xffffffffu, rmax0, 2));
        rmax1 = fmaxf(rmax1, __shfl_xor_sync(0xffffffffu, rmax1, 1));
        rmax1 = fmaxf(rmax1, __shfl_xor_sync(0xffffffffu, rmax1, 2));
        float mn0 = fmaxf(m0, rmax0), mn1 = fmaxf(m1, rmax1);
        float al0 = exp2f(m0 - mn0), al1 = exp2f(m1 - mn1);
        m0 = mn0; m1 = mn1;
        float ps0 = 0.f, ps1 = 0.f;
        #pragma unroll
        for (int nf = 0; nf < 8; nf++) {
            float p0 = exp2f(sa[nf][0] - mn0);
            float p1 = exp2f(sa[nf][1] - mn0);
            float p2 = exp2f(sa[nf][2] - mn1);
            float p3 = exp2f(sa[nf][3] - mn1);
            ps0 += p0 + p1; ps1 += p2 + p3;
            sa[nf][0] = p0; sa[nf][1] = p1; sa[nf][2] = p2; sa[nf][3] = p3;
        }
        ps0 += __shfl_xor_sync(0xffffffffu, ps0, 1);
        ps0 += __shfl_xor_sync(0xffffffffu, ps0, 2);
        ps1 += __shfl_xor_sync(0xffffffffu, ps1, 1);
        ps1 += __shfl_xor_sync(0xffffffffu, ps1, 2);
        l0 = l0 * al0 + ps0;
        l1 = l1 * al1 + ps1;
        #pragma unroll
        for (int nf = 0; nf < 8; nf++) {
            oa[nf][0] *= al0; oa[nf][1] *= al0;
            oa[nf][2] *= al1; oa[nf][3] *= al1;
        }

        // ---- O += P @ V ----
        #pragma unroll
        for (int ks = 0; ks < 4; ks++) {
            uint32_t a[4];
            a[0] = h2u(__floats2half2_rn(sa[2*ks][0],   sa[2*ks][1]));
            a[1] = h2u(__floats2half2_rn(sa[2*ks][2],   sa[2*ks][3]));
            a[2] = h2u(__floats2half2_rn(sa[2*ks+1][0], sa[2*ks+1][1]));
            a[3] = h2u(__floats2half2_rn(sa[2*ks+1][2], sa[2*ks+1][3]));
            #pragma unroll
            for (int np = 0; np < 4; np++) {
                uint32_t q[4];
                ldsm_x4_t(q, vbase + (uint32_t)ks * (16u*144u) + (uint32_t)np * 32u);
                uint32_t b0[2] = {q[0], q[1]}, b1[2] = {q[2], q[3]};
                mma_f16(oa[2*np],   a, b0);
                mma_f16(oa[2*np+1], a, b1);
            }
        }

        st = (st + 1 >= 3) ? 0 : st + 1;
    }

    // ---- epilogue ----
    float inv0 = 1.0f / l0, inv1 = 1.0f / l1;
    size_t r0 = (size_t)(b*CN + q0 + wid*16 + g) * CD + h*64;
    size_t r1 = (size_t)(b*CN + q0 + wid*16 + g + 8) * CD + h*64;
    #pragma unroll
    for (int nf = 0; nf < 8; nf++) {
        int col = nf*8 + 2*c;
        *(uint32_t*)(o + r0 + col) = h2u(__floats2half2_rn(oa[nf][0]*inv0, oa[nf][1]*inv0));
        *(uint32_t*)(o + r1 + col) = h2u(__floats2half2_rn(oa[nf][2]*inv1, oa[nf][3]*inv1));
    }
}

// ---------------- launch ----------------
extern "C" void kernel_launch(void* const* d_in, const int* in_sizes, int n_in,
                              void* d_out, int out_size)
{
    const float* x      = (const float*)d_in[0];
    const int*   ids    = (const int*)  d_in[1];
    const float* n1w    = (const float*)d_in[2];
    const float* n1b    = (const float*)d_in[3];
    const float* pin_w  = (const float*)d_in[4];
    const float* pout_w = (const float*)d_in[5];
    const float* pout_b = (const float*)d_in[6];
    const float* n2w    = (const float*)d_in[7];
    const float* n2b    = (const float*)d_in[8];
    const float* l1w    = (const float*)d_in[9];
    const float* l1b    = (const float*)d_in[10];
    const float* l2w    = (const float*)d_in[11];
    const float* l2b    = (const float*)d_in[12];
    float* out = (float*)d_out;

    __half *xnh, *qkvh, *aoh, *x2h, *hhh, *wqh, *woh, *w1h, *w2h;
    float *xnf, *x1f, *x2f;
    cudaGetSymbolAddress((void**)&xnh,  g_xn_h);
    cudaGetSymbolAddress((void**)&xnf,  g_xn_f);
    cudaGetSymbolAddress((void**)&qkvh, g_qkv_h);
    cudaGetSymbolAddress((void**)&aoh,  g_ao_h);
    cudaGetSymbolAddress((void**)&x1f,  g_x1_f);
    cudaGetSymbolAddress((void**)&x2h,  g_x2_h);
    cudaGetSymbolAddress((void**)&x2f,  g_x2_f);
    cudaGetSymbolAddress((void**)&hhh,  g_h_h);
    cudaGetSymbolAddress((void**)&wqh,  g_wq_h);
    cudaGetSymbolAddress((void**)&woh,  g_wo_h);
    cudaGetSymbolAddress((void**)&w1h,  g_w1_h);
    cudaGetSymbolAddress((void**)&w2h,  g_w2_h);

    cudaFuncSetAttribute(flashm_k,    cudaFuncAttributeMaxDynamicSharedMemorySize, FSM_TOT);
    cudaFuncSetAttribute(gemm_mma<0>, cudaFuncAttributeMaxDynamicSharedMemorySize, GSMEM);
    cudaFuncSetAttribute(gemm_mma<1>, cudaFuncAttributeMaxDynamicSharedMemorySize, GSMEM);
    cudaFuncSetAttribute(gemm_mma<2>, cudaFuncAttributeMaxDynamicSharedMemorySize, GSMEM);

    // 0+1) fused: LN1 + weights->fp16
    ln1_round_k<<<NTOK + NRBLK, 256>>>(
        x, n1w, n1b, xnh, xnf,
        (const float4*)pin_w, (const float4*)pout_w, (const float4*)l1w, (const float4*)l2w,
        (uint2*)wqh, (uint2*)woh, (uint2*)w1h, (uint2*)w2h);

    // 2) qkv = xn @ Wq^T  (fp16 out)
    gemm_mma<0><<<dim3(3*CD/128, NTOK/128), 256, GSMEM>>>(xnh, wqh, nullptr, nullptr, qkvh, NTOK, 3*CD, CD);
    // 3) flash attention -> ao (fp16)
    flashm_k<<<dim3(CN/128, CH, CB), 256, FSM_TOT>>>(qkvh, ids, aoh);
    // 4) x1 = ao @ Wo^T + bout + xn  (fp32 out)
    gemm_mma<1><<<dim3(CD/128, NTOK/128), 256, GSMEM>>>(aoh, woh, pout_b, xnf, x1f, NTOK, CD, CD);
    // 5) x2 = LN2(x1)
    layernorm_k<<<NTOK, 256>>>(x1f, n2w, n2b, x2h, x2f);
    // 6) h = gelu(x2 @ W1^T + b1)  (fp16 out)
    gemm_mma<2><<<dim3(CFF/128, NTOK/128), 256, GSMEM>>>(x2h, w1h, l1b, nullptr, hhh, NTOK, CFF, CD);
    // 7) out = h @ W2^T + b2 + x2  (fp32 out)
    gemm_mma<1><<<dim3(CD/128, NTOK/128), 256, GSMEM>>>(hhh, w2h, l2b, x2f, out, NTOK, CD, CFF);
}